// round 13
// baseline (speedup 1.0000x reference)
#include <cuda_runtime.h>
#include <cuda_fp16.h>
#include <math.h>
#include <stdint.h>

#define BB   512
#define TT   128
#define DIN  256
#define HH   1024
#define G4   4096          // 4*HH
#define MTOT (TT*BB)       // 65536
#define CK   64            // k per chunk (64 fp16 = 128B rows)
#define NBLK 128           // persistent grid (1 block/SM, co-resident)

// ---------------- scratch (device globals: no allocations allowed) ----------
__device__ float g_X [(size_t)TT * BB * G4];   // gate pre-activations (cols n=j*4+g)
__device__ float g_H2[(size_t)TT * BB * HH];   // layer-2 fp32 hidden history (head)
__device__ float g_br1[G4];
__device__ float g_br2[G4];

// fp16 B operands, transposed + gate-interleaved [n=j*4+g][k]:
//   slot 0 = U1, slot 1 = U2, slot 2 = W2   (k < HH)
__device__ __half g_B16[3][(size_t)G4 * HH];
__device__ __half g_W1h[(size_t)G4 * DIN];     // W1 [n][k], k < DIN
__device__ __half g_A1h[(size_t)MTOT * DIN];   // chars fp16, row m = t*BB+b
// h ping-pong fp16: [parity][m*HH + j]  (parity 0 slot never read at t=0)
__device__ __half g_h16[2][(size_t)BB * HH];
// layer-1 fp16 hidden history (A operand of layer-2 input GEMM)
__device__ __half g_Hh16[(size_t)MTOT * HH];

// grid barrier state
__device__ unsigned g_bar_cnt;
__device__ unsigned g_bar_gen;

// ---------------- helpers ----------------------------------------------------
__device__ __forceinline__ uint32_t smem_to_u32(const void* p) {
    uint32_t a;
    asm("{ .reg .u64 t; cvta.to.shared.u64 t, %1; cvt.u32.u64 %0, t; }"
        : "=r"(a) : "l"(p));
    return a;
}
#define SMEM_SWIZZLE_128B(b) ((b) ^ (((b) >> 3) & 0x70))

__device__ __forceinline__ void cp16(uint32_t dst, const void* src) {
    asm volatile("cp.async.cg.shared.global [%0], [%1], 16;" :: "r"(dst), "l"(src));
}
#define CP_COMMIT() asm volatile("cp.async.commit_group;" ::: "memory")
#define CP_WAIT(n)  asm volatile("cp.async.wait_group %0;" :: "n"(n) : "memory")

__device__ __forceinline__ void ldsm4(uint32_t* r, uint32_t addr) {
    asm volatile("ldmatrix.sync.aligned.m8n8.x4.shared.b16 {%0,%1,%2,%3}, [%4];"
        : "=r"(r[0]), "=r"(r[1]), "=r"(r[2]), "=r"(r[3]) : "r"(addr));
}
__device__ __forceinline__ void mma16816h(float* d, const uint32_t* a, const uint32_t* b) {
    asm volatile("mma.sync.aligned.m16n8k16.row.col.f32.f16.f16.f32 "
        "{%0,%1,%2,%3}, {%4,%5,%6,%7}, {%8,%9}, {%0,%1,%2,%3};"
        : "+f"(d[0]), "+f"(d[1]), "+f"(d[2]), "+f"(d[3])
        : "r"(a[0]), "r"(a[1]), "r"(a[2]), "r"(a[3]), "r"(b[0]), "r"(b[1]));
}

// fast activations (abs err ~1e-6; negligible vs fp16 scheme error)
__device__ __forceinline__ float fsig(float x) {
    return __fdividef(1.f, 1.f + __expf(-x));
}
__device__ __forceinline__ float ftanh_(float x) {
    return 1.f - __fdividef(2.f, __expf(2.f * x) + 1.f);
}

// ============================================================================
// Prep kernels
// ============================================================================
__global__ void bias_kernel(const float* __restrict__ b1, const float* __restrict__ b2)
{
    int i = blockIdx.x * blockDim.x + threadIdx.x;
    if (i < G4) {
        int j = i >> 2, g = i & 3;
        g_br1[i] = b1[g * HH + j];
        g_br2[i] = b2[g * HH + j];
    }
    if (i == 0) { g_bar_cnt = 0u; g_bar_gen = 0u; }
}

__global__ void reset_bar_kernel()
{
    if (threadIdx.x == 0) { g_bar_cnt = 0u; g_bar_gen = 0u; }
}

// [k][G4] fp32 -> [n=j*4+g][k<HH] fp16
__global__ void cvt_B_kernel(const float* __restrict__ M, int slot)
{
    int i = blockIdx.x * blockDim.x + threadIdx.x;
    if (i >= G4 * HH) return;
    int n = i >> 10, k = i & 1023;
    int j = n >> 2, g = n & 3;
    g_B16[slot][i] = __float2half(M[(size_t)k * G4 + g * HH + j]);
}

// W1 [k<DIN][G4] -> [n][k] fp16
__global__ void cvt_W1_kernel(const float* __restrict__ W1)
{
    int i = blockIdx.x * blockDim.x + threadIdx.x;
    if (i >= G4 * DIN) return;
    int n = i >> 8, k = i & 255;
    int j = n >> 2, g = n & 3;
    g_W1h[i] = __float2half(W1[(size_t)k * G4 + g * HH + j]);
}

// chars [b][t][k] fp32 -> A1 [m=t*BB+b][k] fp16
__global__ void cvt_chars_kernel(const float* __restrict__ chars)
{
    int i = blockIdx.x * blockDim.x + threadIdx.x;
    if (i >= MTOT * DIN) return;
    int m = i >> 8, k = i & 255;
    int t = m >> 9, b = m & 511;
    g_A1h[i] = __float2half(chars[((size_t)b * TT + t) * DIN + k]);
}

// ============================================================================
// fp16 mma machinery: 128x128 tile, 512 thr, 16 warps (4x4), warp tile 32x32,
// 3-stage cp.async; stage = A 16KB + B 16KB = 32KB. (proven R10/R11 core)
// ============================================================================
#define STAGE_BYTES 32768
#define SM_STEP_TOTAL (3 * STAGE_BYTES)   // 98304

template<int KD>
__device__ __forceinline__ void issue_A_st(uint32_t sb, int stage, int kt,
                                           const __half* Aptr, int m0, int tid)
{
    uint32_t aA = sb + stage * STAGE_BYTES;
    #pragma unroll
    for (int i = 0; i < 2; i++) {
        int idx = tid + 512 * i;
        int row = idx >> 3, cs = idx & 7;
        uint32_t off = SMEM_SWIZZLE_128B((uint32_t)(row * 128 + cs * 16));
        cp16(aA + off, Aptr + (size_t)(m0 + row) * KD + kt + cs * 8);
    }
}
template<int KD>
__device__ __forceinline__ void issue_B_st(uint32_t sb, int stage, int kt,
                                           const __half* Bptr, int nrow0, int tid)
{
    uint32_t bB = sb + stage * STAGE_BYTES + 16384;
    #pragma unroll
    for (int i = 0; i < 2; i++) {
        int idx = tid + 512 * i;
        int row = idx >> 3, cs = idx & 7;
        uint32_t off = SMEM_SWIZZLE_128B((uint32_t)(row * 128 + cs * 16));
        cp16(bB + off, Bptr + (size_t)(nrow0 + row) * KD + kt + cs * 8);
    }
}

// one chunk of compute from a given stage
__device__ __forceinline__ void compute_stage(uint32_t sb, int stage,
                                              int m_warp, int n_warp,
                                              int rsel, int csel, float acc[2][4][4])
{
    const uint32_t base = sb + stage * STAGE_BYTES;
    const uint32_t sA = base;
    const uint32_t sB = base + 16384;
    #pragma unroll
    for (int s = 0; s < 4; s++) {
        uint32_t aF[2][4], bF[4][2];
        #pragma unroll
        for (int mf = 0; mf < 2; mf++) {
            uint32_t off = SMEM_SWIZZLE_128B(
                (uint32_t)((m_warp + mf * 16 + rsel) * 128 + s * 32 + csel));
            ldsm4(aF[mf], sA + off);
        }
        #pragma unroll
        for (int nb = 0; nb < 2; nb++) {
            uint32_t off = SMEM_SWIZZLE_128B(
                (uint32_t)((n_warp + nb * 16 + rsel) * 128 + s * 32 + csel));
            uint32_t r[4];
            ldsm4(r, sB + off);
            bF[nb * 2][0] = r[0];     bF[nb * 2][1] = r[2];
            bF[nb * 2 + 1][0] = r[1]; bF[nb * 2 + 1][1] = r[3];
        }
        #pragma unroll
        for (int mf = 0; mf < 2; mf++)
            #pragma unroll
            for (int nf = 0; nf < 4; nf++)
                mma16816h(acc[mf][nf], aF[mf], bF[nf]);
    }
}

// batched-GEMM mainloop (input GEMMs): stage(c) = c%3, commits inside
template<int KD>
__device__ __forceinline__ void mma_mainloop(
    uint32_t sb, const __half* Aptr, const __half* Bptr,
    int m0, int nrow0, int tid, int m_warp, int n_warp,
    int rsel, int csel, float acc[2][4][4])
{
    const int NC = KD / CK;
    issue_A_st<KD>(sb, 0, 0, Aptr, m0, tid);
    issue_B_st<KD>(sb, 0, 0, Bptr, nrow0, tid);
    CP_COMMIT();
    issue_A_st<KD>(sb, 1, CK, Aptr, m0, tid);
    issue_B_st<KD>(sb, 1, CK, Bptr, nrow0, tid);
    CP_COMMIT();

    for (int c = 0; c < NC; c++) {
        if (c + 1 < NC) { CP_WAIT(1); } else { CP_WAIT(0); }
        __syncthreads();
        if (c + 2 < NC) {
            issue_A_st<KD>(sb, (c + 2) % 3, (c + 2) * CK, Aptr, m0, tid);
            issue_B_st<KD>(sb, (c + 2) % 3, (c + 2) * CK, Bptr, nrow0, tid);
            CP_COMMIT();
        }
        compute_stage(sb, c % 3, m_warp, n_warp, rsel, csel, acc);
        __syncthreads();
    }
}

// stage acc -> zs with given stride
__device__ __forceinline__ void stage_z(float* zs, int stride, const float acc[2][4][4],
                                        int m_warp, int n_warp, int lane)
{
    #pragma unroll
    for (int mf = 0; mf < 2; mf++)
        #pragma unroll
        for (int nf = 0; nf < 4; nf++)
            #pragma unroll
            for (int d = 0; d < 4; d++) {
                int m = m_warp + mf * 16 + (lane >> 2) + (d >> 1) * 8;
                int n = n_warp + nf * 8 + (lane & 3) * 2 + (d & 1);
                zs[m * stride + n] = acc[mf][nf][d];
            }
}

// ============================================================================
// Persistent LSTM layer kernel: 128 fused timesteps, 128 blocks (1/SM).
// c in registers; t=0 shortcut (z=0); cross-step B prefetch; stage(c)=(c+2)%3
// so zs (stride 128 = stages 0+1 exactly) never touches the prefetch stage 2.
// ============================================================================
__global__ __launch_bounds__(512, 1)
void lstm_layer_mma(int layer)
{
    extern __shared__ __align__(128) char smem[];
    const uint32_t sb = smem_to_u32(smem);
    const int tid  = threadIdx.x;
    const int wid  = tid >> 5;
    const int lane = tid & 31;
    const int nrow0 = blockIdx.x * 128;
    const int m0    = blockIdx.y * 128;
    const int j0    = blockIdx.x * 32;

    const __half* B = g_B16[layer];
    const int m_warp = (wid & 3) * 32;
    const int n_warp = (wid >> 2) * 32;
    const int rsel = lane & 15;
    const int csel = (lane >> 4) * 16;

    float creg[8];
    #pragma unroll
    for (int r = 0; r < 8; r++) creg[r] = 0.f;

    float* zs = (float*)smem;    // [128][128] fp32 = 64KB = stages 0+1

    for (int t = 0; t < TT; t++) {
        const int par = t & 1;

        float acc[2][4][4];
        #pragma unroll
        for (int mf = 0; mf < 2; mf++)
            #pragma unroll
            for (int nf = 0; nf < 4; nf++)
                #pragma unroll
                for (int d = 0; d < 4; d++) acc[mf][nf][d] = 0.f;

        if (t > 0) {
            // chunk0 (stage 2) and chunk1 (stage 0) groups already in flight
            for (int c = 0; c < 16; c++) {
                if (c + 1 < 16) { CP_WAIT(1); } else { CP_WAIT(0); }
                __syncthreads();
                if (c + 2 < 16) {
                    int st = (c + 2 + 2) % 3;
                    issue_A_st<HH>(sb, st, (c + 2) * CK, g_h16[par], m0, tid);
                    issue_B_st<HH>(sb, st, (c + 2) * CK, B, nrow0, tid);
                    CP_COMMIT();
                }
                compute_stage(sb, (c + 2) % 3, m_warp, n_warp, rsel, csel, acc);
                __syncthreads();
            }
        }

        // prefetch next step's B chunk0 into free stage 2 (overlaps epilogue)
        if (t + 1 < TT)
            issue_B_st<HH>(sb, 2, 0, B, nrow0, tid);   // uncommitted

        stage_z(zs, 128, acc, m_warp, n_warp, lane);
        __syncthreads();

        // ---------------- epilogue (c in registers) -------------------------
        __half* nh16 = g_h16[par ^ 1];
        #pragma unroll
        for (int r = 0; r < 8; r++) {
            int e  = tid + 512 * r;
            int m  = e >> 5;
            int jl = e & 31;
            int mg = m0 + m;
            int j  = j0 + jl;
            float4 z = *(const float4*)&zs[m * 128 + jl * 4];
            const float* Xrow = g_X + ((size_t)t * BB + mg) * G4 + nrow0;
            float4 xz = *(const float4*)(Xrow + jl * 4);
            float ig = fsig(z.x + xz.x);
            float fg = fsig(z.y + xz.y);
            float gg = ftanh_(z.z + xz.z);
            float og = fsig(z.w + xz.w);
            float cc = fg * creg[r] + ig * gg;
            creg[r] = cc;
            float h = og * ftanh_(cc);
            __half h16v = __float2half(h);
            nh16[(size_t)mg * HH + j] = h16v;
            if (layer == 0)
                g_Hh16[((size_t)t * BB + mg) * HH + j] = h16v;
            else
                g_H2[((size_t)t * BB + mg) * HH + j] = h;
        }

        if (t + 1 < TT) {
            __threadfence();
            __syncthreads();
            // grid barrier
            if (tid == 0) {
                unsigned prev = atomicAdd(&g_bar_cnt, 1u);
                if (prev == NBLK - 1) {
                    atomicExch(&g_bar_cnt, 0u);
                    __threadfence();
                    atomicAdd(&g_bar_gen, 1u);
                } else {
                    for (;;) {
                        unsigned g;
                        asm volatile("ld.acquire.gpu.u32 %0, [%1];" : "=r"(g) : "l"(&g_bar_gen));
                        if (g >= (unsigned)(t + 1)) break;
                        __nanosleep(32);
                    }
                }
            }
            __syncthreads();
            // next step's A chunk0 (joins the prefetched-B group), then chunk1
            issue_A_st<HH>(sb, 2, 0, g_h16[par ^ 1], m0, tid);
            CP_COMMIT();
            issue_A_st<HH>(sb, 0, CK, g_h16[par ^ 1], m0, tid);
            issue_B_st<HH>(sb, 0, CK, B, nrow0, tid);
            CP_COMMIT();
        }
    }
}

// ============================================================================
// Layer-1 input GEMM via fp16 mma (K=256): g_X = A1h @ W1h^T + br1
// ============================================================================
__global__ __launch_bounds__(512, 1)
void gemm1_mma_kernel()
{
    extern __shared__ __align__(128) char smem[];
    const uint32_t sb = smem_to_u32(smem);
    const int tid  = threadIdx.x;
    const int wid  = tid >> 5;
    const int lane = tid & 31;
    const int nrow0 = blockIdx.x * 128;
    const int m0    = blockIdx.y * 128;

    const int m_warp = (wid & 3) * 32;
    const int n_warp = (wid >> 2) * 32;
    const int rsel = lane & 15;
    const int csel = (lane >> 4) * 16;

    float acc[2][4][4];
    #pragma unroll
    for (int mf = 0; mf < 2; mf++)
        #pragma unroll
        for (int nf = 0; nf < 4; nf++)
            #pragma unroll
            for (int d = 0; d < 4; d++) acc[mf][nf][d] = 0.f;

    mma_mainloop<DIN>(sb, g_A1h, g_W1h, m0, nrow0, tid,
                      m_warp, n_warp, rsel, csel, acc);

    float* zs = (float*)smem;
    stage_z(zs, 132, acc, m_warp, n_warp, lane);
    __syncthreads();

    #pragma unroll
    for (int r = 0; r < 8; r++) {
        int e  = tid + 512 * r;
        int m  = e >> 5;
        int jl = e & 31;
        int mg = m0 + m;
        int n  = nrow0 + jl * 4;
        float4 z = *(const float4*)&zs[m * 132 + jl * 4];
        float4 v;
        v.x = z.x + g_br1[n + 0];
        v.y = z.y + g_br1[n + 1];
        v.z = z.z + g_br1[n + 2];
        v.w = z.w + g_br1[n + 3];
        *(float4*)&g_X[(size_t)mg * G4 + n] = v;
    }
}

// ============================================================================
// Layer-2 input GEMM via fp16 mma (K=1024): g_X = H1h16 @ W2h^T + br2
// ============================================================================
__global__ __launch_bounds__(512, 1)
void gemm2_mma_kernel()
{
    extern __shared__ __align__(128) char smem[];
    const uint32_t sb = smem_to_u32(smem);
    const int tid  = threadIdx.x;
    const int wid  = tid >> 5;
    const int lane = tid & 31;
    const int nrow0 = blockIdx.x * 128;
    const int m0    = blockIdx.y * 128;

    const int m_warp = (wid & 3) * 32;
    const int n_warp = (wid >> 2) * 32;
    const int rsel = lane & 15;
    const int csel = (lane >> 4) * 16;

    float acc[2][4][4];
    #pragma unroll
    for (int mf = 0; mf < 2; mf++)
        #pragma unroll
        for (int nf = 0; nf < 4; nf++)
            #pragma unroll
            for (int d = 0; d < 4; d++) acc[mf][nf][d] = 0.f;

    mma_mainloop<HH>(sb, g_Hh16, g_B16[2], m0, nrow0, tid,
                     m_warp, n_warp, rsel, csel, acc);

    float* zs = (float*)smem;
    stage_z(zs, 132, acc, m_warp, n_warp, lane);
    __syncthreads();

    #pragma unroll
    for (int r = 0; r < 8; r++) {
        int e  = tid + 512 * r;
        int m  = e >> 5;
        int jl = e & 31;
        int mg = m0 + m;
        int n  = nrow0 + jl * 4;
        float4 z = *(const float4*)&zs[m * 132 + jl * 4];
        float4 v;
        v.x = z.x + g_br2[n + 0];
        v.y = z.y + g_br2[n + 1];
        v.z = z.z + g_br2[n + 2];
        v.w = z.w + g_br2[n + 3];
        *(float4*)&g_X[(size_t)mg * G4 + n] = v;
    }
}

// ---------------- output head ------------------------------------------------
__global__ void dense_out_kernel(const int* __restrict__ seq,
                                 const float* __restrict__ Wd,
                                 const float* __restrict__ bd,
                                 float* __restrict__ out)
{
    int b   = blockIdx.x;
    int tid = threadIdx.x;   // 128 threads
    const float* hrow = g_H2 + ((size_t)(seq[b] - 1) * BB + b) * HH;
    float s0 = 0.f, s1 = 0.f, s2 = 0.f;
    for (int j = tid; j < HH; j += 128) {
        float h = hrow[j];
        s0 += h * Wd[j * 3 + 0];
        s1 += h * Wd[j * 3 + 1];
        s2 += h * Wd[j * 3 + 2];
    }
    __shared__ float sm[3][128];
    sm[0][tid] = s0; sm[1][tid] = s1; sm[2][tid] = s2;
    __syncthreads();
    for (int s = 64; s > 0; s >>= 1) {
        if (tid < s) {
            sm[0][tid] += sm[0][tid + s];
            sm[1][tid] += sm[1][tid + s];
            sm[2][tid] += sm[2][tid + s];
        }
        __syncthreads();
    }
    if (tid == 0) {
        out[b * 3 + 0] = fmaxf(sm[0][0] + bd[0], 0.f);
        out[b * 3 + 1] = fmaxf(sm[1][0] + bd[1], 0.f);
        out[b * 3 + 2] = fmaxf(sm[2][0] + bd[2], 0.f);
    }
}

// ---------------- launch -----------------------------------------------------
extern "C" void kernel_launch(void* const* d_in, const int* in_sizes, int n_in,
                              void* d_out, int out_size)
{
    const float* chars = (const float*)d_in[0];
    const int*   seq   = (const int*)  d_in[1];
    const float* W1    = (const float*)d_in[2];
    const float* U1    = (const float*)d_in[3];
    const float* b1    = (const float*)d_in[4];
    const float* W2    = (const float*)d_in[5];
    const float* U2    = (const float*)d_in[6];
    const float* b2    = (const float*)d_in[7];
    const float* Wd    = (const float*)d_in[8];
    const float* bd    = (const float*)d_in[9];
    float*       out   = (float*)d_out;

    cudaFuncSetAttribute(lstm_layer_mma,   cudaFuncAttributeMaxDynamicSharedMemorySize, SM_STEP_TOTAL);
    cudaFuncSetAttribute(gemm1_mma_kernel, cudaFuncAttributeMaxDynamicSharedMemorySize, SM_STEP_TOTAL);
    cudaFuncSetAttribute(gemm2_mma_kernel, cudaFuncAttributeMaxDynamicSharedMemorySize, SM_STEP_TOTAL);

    dim3 gG(G4 / 128, MTOT / 128);   // 32 x 512 (input GEMMs)
    dim3 gS(G4 / 128, BB / 128);     // 32 x 4 = 128 persistent blocks

    // --- prep ---
    bias_kernel<<<(G4 + 255) / 256, 256>>>(b1, b2);
    cvt_B_kernel<<<(G4 * HH + 255) / 256, 256>>>(U1, 0);
    cvt_B_kernel<<<(G4 * HH + 255) / 256, 256>>>(U2, 1);
    cvt_B_kernel<<<(G4 * HH + 255) / 256, 256>>>(W2, 2);
    cvt_W1_kernel<<<(G4 * DIN + 255) / 256, 256>>>(W1);
    cvt_chars_kernel<<<(MTOT * DIN + 255) / 256, 256>>>(chars);

    // --- layer 1 ---
    gemm1_mma_kernel<<<gG, 512, SM_STEP_TOTAL>>>();
    reset_bar_kernel<<<1, 32>>>();
    lstm_layer_mma<<<gS, 512, SM_STEP_TOTAL>>>(0);

    // --- layer 2 ---
    gemm2_mma_kernel<<<gG, 512, SM_STEP_TOTAL>>>();
    reset_bar_kernel<<<1, 32>>>();
    lstm_layer_mma<<<gS, 512, SM_STEP_TOTAL>>>(1);

    // --- gather + dense + relu ---
    dense_out_kernel<<<BB, 128>>>(seq, Wd, bd, out);
}

// round 14
// speedup vs baseline: 1.1116x; 1.1116x over previous
#include <cuda_runtime.h>
#include <cuda_fp16.h>
#include <math.h>
#include <stdint.h>

#define BB   512
#define TT   128
#define DIN  256
#define HH   1024
#define G4   4096          // 4*HH
#define MTOT (TT*BB)       // 65536
#define CK   64            // k per chunk (64 fp16 = 128B rows)

// ---------------- scratch (device globals: no allocations allowed) ----------
__device__ float g_X [(size_t)TT * BB * G4];   // gate pre-activations (cols n=j*4+g)
__device__ float g_H2[(size_t)TT * BB * HH];   // layer-2 fp32 hidden history (head)
__device__ float g_c [BB * HH];                // cell state (reused per layer)
__device__ float g_br1[G4];
__device__ float g_br2[G4];

// fp16 B operands, transposed + gate-interleaved [n=j*4+g][k]:
//   slot 0 = U1, slot 1 = U2, slot 2 = W2   (k < HH)
__device__ __half g_B16[3][(size_t)G4 * HH];
__device__ __half g_W1h[(size_t)G4 * DIN];     // W1 [n][k], k < DIN
__device__ __half g_A1h[(size_t)MTOT * DIN];   // chars fp16, row m = t*BB+b
// h ping-pong fp16: [parity][m*HH + j]
__device__ __half g_h16[2][(size_t)BB * HH];
// layer-1 fp16 hidden history (A operand of layer-2 input GEMM)
__device__ __half g_Hh16[(size_t)MTOT * HH];

// ---------------- helpers ----------------------------------------------------
__device__ __forceinline__ uint32_t smem_to_u32(const void* p) {
    uint32_t a;
    asm("{ .reg .u64 t; cvta.to.shared.u64 t, %1; cvt.u32.u64 %0, t; }"
        : "=r"(a) : "l"(p));
    return a;
}
#define SMEM_SWIZZLE_128B(b) ((b) ^ (((b) >> 3) & 0x70))

__device__ __forceinline__ void cp16(uint32_t dst, const void* src) {
    asm volatile("cp.async.cg.shared.global [%0], [%1], 16;" :: "r"(dst), "l"(src));
}
#define CP_COMMIT() asm volatile("cp.async.commit_group;" ::: "memory")
#define CP_WAIT(n)  asm volatile("cp.async.wait_group %0;" :: "n"(n) : "memory")

__device__ __forceinline__ void ldsm4(uint32_t* r, uint32_t addr) {
    asm volatile("ldmatrix.sync.aligned.m8n8.x4.shared.b16 {%0,%1,%2,%3}, [%4];"
        : "=r"(r[0]), "=r"(r[1]), "=r"(r[2]), "=r"(r[3]) : "r"(addr));
}
__device__ __forceinline__ void mma16816h(float* d, const uint32_t* a, const uint32_t* b) {
    asm volatile("mma.sync.aligned.m16n8k16.row.col.f32.f16.f16.f32 "
        "{%0,%1,%2,%3}, {%4,%5,%6,%7}, {%8,%9}, {%0,%1,%2,%3};"
        : "+f"(d[0]), "+f"(d[1]), "+f"(d[2]), "+f"(d[3])
        : "r"(a[0]), "r"(a[1]), "r"(a[2]), "r"(a[3]), "r"(b[0]), "r"(b[1]));
}

// fast activations (abs err ~1e-6; negligible vs fp16 scheme error)
__device__ __forceinline__ float fsig(float x) {
    return __fdividef(1.f, 1.f + __expf(-x));
}
__device__ __forceinline__ float ftanh_(float x) {
    return 1.f - __fdividef(2.f, __expf(2.f * x) + 1.f);
}

// ============================================================================
// Prep kernels
// ============================================================================
__global__ void bias_kernel(const float* __restrict__ b1, const float* __restrict__ b2)
{
    int i = blockIdx.x * blockDim.x + threadIdx.x;
    if (i < G4) {
        int j = i >> 2, g = i & 3;
        g_br1[i] = b1[g * HH + j];
        g_br2[i] = b2[g * HH + j];
    }
}

// [k][G4] fp32 -> [n=j*4+g][k<HH] fp16
__global__ void cvt_B_kernel(const float* __restrict__ M, int slot)
{
    int i = blockIdx.x * blockDim.x + threadIdx.x;
    if (i >= G4 * HH) return;
    int n = i >> 10, k = i & 1023;
    int j = n >> 2, g = n & 3;
    g_B16[slot][i] = __float2half(M[(size_t)k * G4 + g * HH + j]);
}

// W1 [k<DIN][G4] -> [n][k] fp16
__global__ void cvt_W1_kernel(const float* __restrict__ W1)
{
    int i = blockIdx.x * blockDim.x + threadIdx.x;
    if (i >= G4 * DIN) return;
    int n = i >> 8, k = i & 255;
    int j = n >> 2, g = n & 3;
    g_W1h[i] = __float2half(W1[(size_t)k * G4 + g * HH + j]);
}

// chars [b][t][k] fp32 -> A1 [m=t*BB+b][k] fp16
__global__ void cvt_chars_kernel(const float* __restrict__ chars)
{
    int i = blockIdx.x * blockDim.x + threadIdx.x;
    if (i >= MTOT * DIN) return;
    int m = i >> 8, k = i & 255;
    int t = m >> 9, b = m & 511;
    g_A1h[i] = __float2half(chars[((size_t)b * TT + t) * DIN + k]);
}

__global__ void zero_state_kernel()
{
    int i = blockIdx.x * blockDim.x + threadIdx.x;
    if (i < BB * HH) {
        g_c[i] = 0.f;
        g_h16[0][i] = __float2half(0.f);
    }
}

// ============================================================================
// fp16 mma machinery: 128-col tiles, warp tile 32(n) wide, SW128 smem.
// ============================================================================
#define STAGE_BYTES 32768                 // M=128 stage: A 16KB + B 16KB
#define SM_CORE (3 * STAGE_BYTES)         // 98304 (gemm1)
#define SM_XOFF SM_CORE                   // step kernel: X tile region
#define SM_STEP (SM_CORE + 65536)         // 163840

template<int KD>
__device__ __forceinline__ void issue_chunk(
    uint32_t sb, int stage, int kt,
    const __half* Aptr, const __half* Bptr,
    int m0, int nrow0, int tid)
{
    uint32_t base = sb + stage * STAGE_BYTES;
    uint32_t aA = base;
    uint32_t bB = base + 16384;
    #pragma unroll
    for (int i = 0; i < 2; i++) {                 // A: 128 rows x 8 x 16B
        int idx = tid + 512 * i;
        int row = idx >> 3, cs = idx & 7;
        uint32_t off = SMEM_SWIZZLE_128B((uint32_t)(row * 128 + cs * 16));
        cp16(aA + off, Aptr + (size_t)(m0 + row) * KD + kt + cs * 8);
    }
    #pragma unroll
    for (int i = 0; i < 2; i++) {                 // B: 128 rows x 8 x 16B
        int idx = tid + 512 * i;
        int row = idx >> 3, cs = idx & 7;
        uint32_t off = SMEM_SWIZZLE_128B((uint32_t)(row * 128 + cs * 16));
        cp16(bB + off, Bptr + (size_t)(nrow0 + row) * KD + kt + cs * 8);
    }
    CP_COMMIT();
}

// one k64 chunk of compute (M=128 layout)
__device__ __forceinline__ void compute_stage(uint32_t sb, int stage,
                                              int m_warp, int n_warp,
                                              int rsel, int csel, float acc[2][4][4])
{
    const uint32_t base = sb + stage * STAGE_BYTES;
    const uint32_t sA = base;
    const uint32_t sB = base + 16384;
    #pragma unroll
    for (int s = 0; s < 4; s++) {
        uint32_t aF[2][4], bF[4][2];
        #pragma unroll
        for (int mf = 0; mf < 2; mf++) {
            uint32_t off = SMEM_SWIZZLE_128B(
                (uint32_t)((m_warp + mf * 16 + rsel) * 128 + s * 32 + csel));
            ldsm4(aF[mf], sA + off);
        }
        #pragma unroll
        for (int nb = 0; nb < 2; nb++) {
            uint32_t off = SMEM_SWIZZLE_128B(
                (uint32_t)((n_warp + nb * 16 + rsel) * 128 + s * 32 + csel));
            uint32_t r[4];
            ldsm4(r, sB + off);
            bF[nb * 2][0] = r[0];     bF[nb * 2][1] = r[2];
            bF[nb * 2 + 1][0] = r[1]; bF[nb * 2 + 1][1] = r[3];
        }
        #pragma unroll
        for (int mf = 0; mf < 2; mf++)
            #pragma unroll
            for (int nf = 0; nf < 4; nf++)
                mma16816h(acc[mf][nf], aF[mf], bF[nf]);
    }
}

template<int KD>
__device__ __forceinline__ void mma_mainloop(
    uint32_t sb, const __half* Aptr, const __half* Bptr,
    int m0, int nrow0, int tid, int m_warp, int n_warp,
    int rsel, int csel, float acc[2][4][4])
{
    const int NC = KD / CK;
    issue_chunk<KD>(sb, 0, 0,  Aptr, Bptr, m0, nrow0, tid);
    issue_chunk<KD>(sb, 1, CK, Aptr, Bptr, m0, nrow0, tid);

    for (int c = 0; c < NC; c++) {
        if (c + 1 < NC) { CP_WAIT(1); } else { CP_WAIT(0); }
        __syncthreads();
        if (c + 2 < NC)
            issue_chunk<KD>(sb, (c + 2) % 3, (c + 2) * CK, Aptr, Bptr, m0, nrow0, tid);
        compute_stage(sb, c % 3, m_warp, n_warp, rsel, csel, acc);
        __syncthreads();
    }
}

// stage acc -> zs (M=128 layout)
__device__ __forceinline__ void stage_z(float* zs, int stride, const float acc[2][4][4],
                                        int m_warp, int n_warp, int lane)
{
    #pragma unroll
    for (int mf = 0; mf < 2; mf++)
        #pragma unroll
        for (int nf = 0; nf < 4; nf++)
            #pragma unroll
            for (int d = 0; d < 4; d++) {
                int m = m_warp + mf * 16 + (lane >> 2) + (d >> 1) * 8;
                int n = n_warp + nf * 8 + (lane & 3) * 2 + (d & 1);
                zs[m * stride + n] = acc[mf][nf][d];
            }
}

// ============================================================================
// Recurrent LSTM step (1-term fp16) + smem X prefetch: grid (32,4), 512 thr
// ============================================================================
__global__ __launch_bounds__(512, 1)
void lstm_step_mma(int t, int layer)
{
    extern __shared__ __align__(128) char smem[];
    const uint32_t sb = smem_to_u32(smem);
    const int tid  = threadIdx.x;
    const int wid  = tid >> 5;
    const int lane = tid & 31;
    const int nrow0 = blockIdx.x * 128;
    const int m0    = blockIdx.y * 128;
    const int par   = t & 1;

    const __half* Aptr = g_h16[par];
    const __half* Bptr = g_B16[layer];
    const int m_warp = (wid & 3) * 32;
    const int n_warp = (wid >> 2) * 32;
    const int rsel = lane & 15;
    const int csel = (lane >> 4) * 16;

    float acc[2][4][4];
    #pragma unroll
    for (int mf = 0; mf < 2; mf++)
        #pragma unroll
        for (int nf = 0; nf < 4; nf++)
            #pragma unroll
            for (int d = 0; d < 4; d++) acc[mf][nf][d] = 0.f;

    // prologue: chunk0, chunk1, then the X-tile group (drained by FIFO waits)
    issue_chunk<HH>(sb, 0, 0,  Aptr, Bptr, m0, nrow0, tid);
    issue_chunk<HH>(sb, 1, CK, Aptr, Bptr, m0, nrow0, tid);
    {
        // X tile: 128 rows x 512B -> smem @ SM_XOFF (plain layout)
        const float* Xbase = g_X + ((size_t)t * BB + m0) * G4 + nrow0;
        #pragma unroll
        for (int i = 0; i < 8; i++) {
            int idx = tid + 512 * i;            // < 4096 16B-chunks
            int row = idx >> 5, cs = idx & 31;
            cp16(sb + SM_XOFF + row * 512 + cs * 16,
                 (const char*)(Xbase + (size_t)row * G4) + cs * 16);
        }
        CP_COMMIT();
    }

    for (int c = 0; c < 16; c++) {
        if (c + 1 < 16) { CP_WAIT(1); } else { CP_WAIT(0); }
        __syncthreads();
        if (c + 2 < 16)
            issue_chunk<HH>(sb, (c + 2) % 3, (c + 2) * CK, Aptr, Bptr, m0, nrow0, tid);
        compute_stage(sb, c % 3, m_warp, n_warp, rsel, csel, acc);
        __syncthreads();
    }

    float* zs = (float*)smem;                 // [128][132] within stages 0-2
    stage_z(zs, 132, acc, m_warp, n_warp, lane);
    __syncthreads();

    const float* Xs = (const float*)(smem + SM_XOFF);
    __half* nh16 = g_h16[par ^ 1];
    const int j0 = blockIdx.x * 32;

    #pragma unroll
    for (int r = 0; r < 8; r++) {
        int e  = tid + 512 * r;
        int m  = e >> 5;
        int jl = e & 31;
        int mg = m0 + m;
        int j  = j0 + jl;
        float4 z  = *(const float4*)&zs[m * 132 + jl * 4];
        float4 xz = *(const float4*)&Xs[m * 128 + jl * 4];
        float ig = fsig(z.x + xz.x);
        float fg = fsig(z.y + xz.y);
        float gg = ftanh_(z.z + xz.z);
        float og = fsig(z.w + xz.w);
        size_t cidx = (size_t)mg * HH + j;
        float cc = fg * g_c[cidx] + ig * gg;
        g_c[cidx] = cc;
        float h = og * ftanh_(cc);
        __half h16v = __float2half(h);
        nh16[cidx] = h16v;
        if (layer == 0)
            g_Hh16[((size_t)t * BB + mg) * HH + j] = h16v;
        else
            g_H2[((size_t)t * BB + mg) * HH + j] = h;
    }
}

// ============================================================================
// Layer-1 input GEMM (K=256, M=128 tiles): g_X = A1h @ W1h^T + br1
// ============================================================================
__global__ __launch_bounds__(512, 1)
void gemm1_mma_kernel()
{
    extern __shared__ __align__(128) char smem[];
    const uint32_t sb = smem_to_u32(smem);
    const int tid  = threadIdx.x;
    const int wid  = tid >> 5;
    const int lane = tid & 31;
    const int nrow0 = blockIdx.x * 128;
    const int m0    = blockIdx.y * 128;

    const int m_warp = (wid & 3) * 32;
    const int n_warp = (wid >> 2) * 32;
    const int rsel = lane & 15;
    const int csel = (lane >> 4) * 16;

    float acc[2][4][4];
    #pragma unroll
    for (int mf = 0; mf < 2; mf++)
        #pragma unroll
        for (int nf = 0; nf < 4; nf++)
            #pragma unroll
            for (int d = 0; d < 4; d++) acc[mf][nf][d] = 0.f;

    mma_mainloop<DIN>(sb, g_A1h, g_W1h, m0, nrow0, tid,
                      m_warp, n_warp, rsel, csel, acc);

    float* zs = (float*)smem;
    stage_z(zs, 132, acc, m_warp, n_warp, lane);
    __syncthreads();

    #pragma unroll
    for (int r = 0; r < 8; r++) {
        int e  = tid + 512 * r;
        int m  = e >> 5;
        int jl = e & 31;
        int mg = m0 + m;
        int n  = nrow0 + jl * 4;
        float4 z = *(const float4*)&zs[m * 132 + jl * 4];
        float4 v;
        v.x = z.x + g_br1[n + 0];
        v.y = z.y + g_br1[n + 1];
        v.z = z.z + g_br1[n + 2];
        v.w = z.w + g_br1[n + 3];
        *(float4*)&g_X[(size_t)mg * G4 + n] = v;
    }
}

// ============================================================================
// Layer-2 input GEMM (K=1024) with 256x128 tiles: g_X = H1h16 @ W2h^T + br2
// grid (32, 256), 512 threads, 16 warps (4m x 4n), warp tile 64x32.
// stage = A 32KB + B 16KB = 48KB; 3 stages = 144KB.
// ============================================================================
#define G2_STAGE 49152
#define G2_TOTAL (3 * G2_STAGE)   // 147456

__device__ __forceinline__ void g2_issue(uint32_t sb, int stage, int kt,
                                         int m0, int nrow0, int tid)
{
    uint32_t base = sb + stage * G2_STAGE;
    uint32_t aA = base;
    uint32_t bB = base + 32768;
    #pragma unroll
    for (int i = 0; i < 4; i++) {                 // A: 256 rows x 8 x 16B
        int idx = tid + 512 * i;
        int row = idx >> 3, cs = idx & 7;
        uint32_t off = SMEM_SWIZZLE_128B((uint32_t)(row * 128 + cs * 16));
        cp16(aA + off, g_Hh16 + (size_t)(m0 + row) * HH + kt + cs * 8);
    }
    #pragma unroll
    for (int i = 0; i < 2; i++) {                 // B: 128 rows x 8 x 16B
        int idx = tid + 512 * i;
        int row = idx >> 3, cs = idx & 7;
        uint32_t off = SMEM_SWIZZLE_128B((uint32_t)(row * 128 + cs * 16));
        cp16(bB + off, g_B16[2] + (size_t)(nrow0 + row) * HH + kt + cs * 8);
    }
    CP_COMMIT();
}

__global__ __launch_bounds__(512, 1)
void gemm2_mma_kernel()
{
    extern __shared__ __align__(128) char smem[];
    const uint32_t sb = smem_to_u32(smem);
    const int tid  = threadIdx.x;
    const int wid  = tid >> 5;
    const int lane = tid & 31;
    const int nrow0 = blockIdx.x * 128;
    const int m0    = blockIdx.y * 256;

    const int m_warp = (wid & 3) * 64;    // 4 m-tiles of 64
    const int n_warp = (wid >> 2) * 32;   // 4 n-tiles of 32
    const int rsel = lane & 15;
    const int csel = (lane >> 4) * 16;

    float acc[4][4][4];
    #pragma unroll
    for (int mf = 0; mf < 4; mf++)
        #pragma unroll
        for (int nf = 0; nf < 4; nf++)
            #pragma unroll
            for (int d = 0; d < 4; d++) acc[mf][nf][d] = 0.f;

    g2_issue(sb, 0, 0,  m0, nrow0, tid);
    g2_issue(sb, 1, CK, m0, nrow0, tid);

    for (int c = 0; c < 16; c++) {
        if (c + 1 < 16) { CP_WAIT(1); } else { CP_WAIT(0); }
        __syncthreads();
        if (c + 2 < 16)
            g2_issue(sb, (c + 2) % 3, (c + 2) * CK, m0, nrow0, tid);

        const uint32_t base = sb + (c % 3) * G2_STAGE;
        const uint32_t sA = base;
        const uint32_t sB = base + 32768;
        #pragma unroll
        for (int s = 0; s < 4; s++) {
            uint32_t aF[4][4], bF[4][2];
            #pragma unroll
            for (int mf = 0; mf < 4; mf++) {
                uint32_t off = SMEM_SWIZZLE_128B(
                    (uint32_t)((m_warp + mf * 16 + rsel) * 128 + s * 32 + csel));
                ldsm4(aF[mf], sA + off);
            }
            #pragma unroll
            for (int nb = 0; nb < 2; nb++) {
                uint32_t off = SMEM_SWIZZLE_128B(
                    (uint32_t)((n_warp + nb * 16 + rsel) * 128 + s * 32 + csel));
                uint32_t r[4];
                ldsm4(r, sB + off);
                bF[nb * 2][0] = r[0];     bF[nb * 2][1] = r[2];
                bF[nb * 2 + 1][0] = r[1]; bF[nb * 2 + 1][1] = r[3];
            }
            #pragma unroll
            for (int mf = 0; mf < 4; mf++)
                #pragma unroll
                for (int nf = 0; nf < 4; nf++)
                    mma16816h(acc[mf][nf], aF[mf], bF[nf]);
        }
        __syncthreads();
    }

    // epilogue: zs [256][132] fp32 = 135KB (fits in 144KB stages)
    float* zs = (float*)smem;
    #pragma unroll
    for (int mf = 0; mf < 4; mf++)
        #pragma unroll
        for (int nf = 0; nf < 4; nf++)
            #pragma unroll
            for (int d = 0; d < 4; d++) {
                int m = m_warp + mf * 16 + (lane >> 2) + (d >> 1) * 8;
                int n = n_warp + nf * 8 + (lane & 3) * 2 + (d & 1);
                zs[m * 132 + n] = acc[mf][nf][d];
            }
    __syncthreads();

    #pragma unroll
    for (int r = 0; r < 16; r++) {
        int e  = tid + 512 * r;          // < 8192
        int m  = e >> 5;
        int jl = e & 31;
        int mg = m0 + m;
        int n  = nrow0 + jl * 4;
        float4 z = *(const float4*)&zs[m * 132 + jl * 4];
        float4 v;
        v.x = z.x + g_br2[n + 0];
        v.y = z.y + g_br2[n + 1];
        v.z = z.z + g_br2[n + 2];
        v.w = z.w + g_br2[n + 3];
        *(float4*)&g_X[(size_t)mg * G4 + n] = v;
    }
}

// ---------------- output head ------------------------------------------------
__global__ void dense_out_kernel(const int* __restrict__ seq,
                                 const float* __restrict__ Wd,
                                 const float* __restrict__ bd,
                                 float* __restrict__ out)
{
    int b   = blockIdx.x;
    int tid = threadIdx.x;   // 128 threads
    const float* hrow = g_H2 + ((size_t)(seq[b] - 1) * BB + b) * HH;
    float s0 = 0.f, s1 = 0.f, s2 = 0.f;
    for (int j = tid; j < HH; j += 128) {
        float h = hrow[j];
        s0 += h * Wd[j * 3 + 0];
        s1 += h * Wd[j * 3 + 1];
        s2 += h * Wd[j * 3 + 2];
    }
    __shared__ float sm[3][128];
    sm[0][tid] = s0; sm[1][tid] = s1; sm[2][tid] = s2;
    __syncthreads();
    for (int s = 64; s > 0; s >>= 1) {
        if (tid < s) {
            sm[0][tid] += sm[0][tid + s];
            sm[1][tid] += sm[1][tid + s];
            sm[2][tid] += sm[2][tid + s];
        }
        __syncthreads();
    }
    if (tid == 0) {
        out[b * 3 + 0] = fmaxf(sm[0][0] + bd[0], 0.f);
        out[b * 3 + 1] = fmaxf(sm[1][0] + bd[1], 0.f);
        out[b * 3 + 2] = fmaxf(sm[2][0] + bd[2], 0.f);
    }
}

// ---------------- launch -----------------------------------------------------
extern "C" void kernel_launch(void* const* d_in, const int* in_sizes, int n_in,
                              void* d_out, int out_size)
{
    const float* chars = (const float*)d_in[0];
    const int*   seq   = (const int*)  d_in[1];
    const float* W1    = (const float*)d_in[2];
    const float* U1    = (const float*)d_in[3];
    const float* b1    = (const float*)d_in[4];
    const float* W2    = (const float*)d_in[5];
    const float* U2    = (const float*)d_in[6];
    const float* b2    = (const float*)d_in[7];
    const float* Wd    = (const float*)d_in[8];
    const float* bd    = (const float*)d_in[9];
    float*       out   = (float*)d_out;

    cudaFuncSetAttribute(lstm_step_mma,    cudaFuncAttributeMaxDynamicSharedMemorySize, SM_STEP);
    cudaFuncSetAttribute(gemm1_mma_kernel, cudaFuncAttributeMaxDynamicSharedMemorySize, SM_CORE);
    cudaFuncSetAttribute(gemm2_mma_kernel, cudaFuncAttributeMaxDynamicSharedMemorySize, G2_TOTAL);

    dim3 g1(G4 / 128, MTOT / 128);   // 32 x 512
    dim3 g2(G4 / 128, MTOT / 256);   // 32 x 256
    dim3 gS(G4 / 128, BB / 128);     // 32 x 4

    // --- prep ---
    bias_kernel<<<(G4 + 255) / 256, 256>>>(b1, b2);
    cvt_B_kernel<<<(G4 * HH + 255) / 256, 256>>>(U1, 0);
    cvt_B_kernel<<<(G4 * HH + 255) / 256, 256>>>(U2, 1);
    cvt_B_kernel<<<(G4 * HH + 255) / 256, 256>>>(W2, 2);
    cvt_W1_kernel<<<(G4 * DIN + 255) / 256, 256>>>(W1);
    cvt_chars_kernel<<<(MTOT * DIN + 255) / 256, 256>>>(chars);

    // --- layer 1 ---
    gemm1_mma_kernel<<<g1, 512, SM_CORE>>>();
    zero_state_kernel<<<(BB * HH + 255) / 256, 256>>>();
    for (int t = 0; t < TT; t++)
        lstm_step_mma<<<gS, 512, SM_STEP>>>(t, 0);

    // --- layer 2 ---
    gemm2_mma_kernel<<<g2, 512, G2_TOTAL>>>();
    zero_state_kernel<<<(BB * HH + 255) / 256, 256>>>();
    for (int t = 0; t < TT; t++)
        lstm_step_mma<<<gS, 512, SM_STEP>>>(t, 1);

    // --- gather + dense + relu ---
    dense_out_kernel<<<BB, 128>>>(seq, Wd, bd, out);
}